// round 15
// baseline (speedup 1.0000x reference)
#include <cuda_runtime.h>
#include <cuda_fp16.h>
#include <math.h>
#include <stdint.h>

#define HID   512
#define PH    32
#define BSZ   2048
#define FOURH 2048
#define SLAB  (BSZ * HID)

#define TM 128
#define TN 128
#define KC 64
#define NCH (HID / KC)   // 8 k-chunks
#define NTHR 256
#define NMB  (BSZ / TM)     // 16 mb row-blocks
#define NNB  (FOURH / TN)   // 16 nb tiles

// stage layout (bytes): A 128x64 fp16 = 16KB, B 128x64 fp16 = 16KB
#define AH_OFF 0
#define BH_OFF 16384
#define STAGE  32768
#define NSTG   3
#define SMEM_DYN (NSTG * STAGE)   // 96KB -> 2 CTAs/SM, all 256 CTAs co-resident

// ---------------- static device scratch ----------------
__device__ __half g_x[(PH + 1) * (size_t)SLAB];   // x_t (fp16), t=0..PH
__device__ __half g_w [FOURH * HID];   // fp16(W_ih + W_hh), permuted
__device__ __half g_w0[FOURH * HID];   // fp16(W_ih), permuted (step 0)
__device__ float g_bp[FOURH];
__device__ float g_c[(size_t)BSZ * HID];
__device__ float g_part[(size_t)PH * NNB * BSZ * 2];   // projection partials
__device__ int   g_cnt[PH][NMB];                       // per-(t,mb) arrival counters

// ---------------- helpers ----------------
__device__ __forceinline__ uint32_t smem_u32(const void* p) {
    uint32_t a;
    asm("{ .reg .u64 t; cvta.to.shared.u64 t, %1; cvt.u32.u64 %0, t; }" : "=r"(a) : "l"(p));
    return a;
}
// 128B rows, 8 x 16B quads, XOR-swizzled: conflict-free for cp.async stores and ldmatrix
__device__ __forceinline__ uint32_t smoff64(int row, int q) {
    return (uint32_t)((row << 7) + (((q) ^ (row & 7)) << 4));
}
__device__ __forceinline__ void cp16(uint32_t dst, const void* src) {
    asm volatile("cp.async.cg.shared.global [%0], [%1], 16;" :: "r"(dst), "l"(src));
}
__device__ __forceinline__ void cp_commit() { asm volatile("cp.async.commit_group;"); }
template <int N>
__device__ __forceinline__ void cp_wait() {
    asm volatile("cp.async.wait_group %0;" :: "n"(N) : "memory");
}
__device__ __forceinline__ void ldsm4(uint32_t* r, uint32_t addr) {
    asm volatile("ldmatrix.sync.aligned.m8n8.x4.shared.b16 {%0,%1,%2,%3}, [%4];"
        : "=r"(r[0]), "=r"(r[1]), "=r"(r[2]), "=r"(r[3]) : "r"(addr));
}
__device__ __forceinline__ void mma16816(float* c, const uint32_t* a,
                                         uint32_t b0, uint32_t b1) {
    asm volatile(
        "mma.sync.aligned.m16n8k16.row.col.f32.f16.f16.f32 "
        "{%0,%1,%2,%3}, {%4,%5,%6,%7}, {%8,%9}, {%0,%1,%2,%3};"
        : "+f"(c[0]), "+f"(c[1]), "+f"(c[2]), "+f"(c[3])
        : "r"(a[0]), "r"(a[1]), "r"(a[2]), "r"(a[3]), "r"(b0), "r"(b1));
}

// ---------------- prep ----------------
// W row r=q*512+hu -> rp = (hu/32)*128 + q*32 + (hu%32): N-tile nb holds 32 units x 4 gates
__global__ void prep_w(const float* __restrict__ Wih, const float* __restrict__ Whh,
                       const float* __restrict__ bih, const float* __restrict__ bhh) {
    int idx = blockIdx.x * blockDim.x + threadIdx.x;
    if (idx >= FOURH * HID) return;
    int r = idx / HID, k = idx - r * HID;
    int q = r >> 9, hu = r & 511;
    int rp = ((hu >> 5) << 7) + (q << 5) + (hu & 31);
    size_t o = (size_t)rp * HID + k;
    g_w0[o] = __float2half_rn(Wih[idx]);
    g_w [o] = __float2half_rn(Wih[idx] + Whh[idx]);
    if (k == 0) g_bp[rp] = bih[r] + bhh[r];
}
__global__ void prep_z(const float* __restrict__ z) {
    int i = blockIdx.x * blockDim.x + threadIdx.x;
    if (i < PH * NMB) ((int*)g_cnt)[i] = 0;   // reset chain counters every launch
    if (i >= BSZ * HID) return;
    g_x[i] = __float2half_rn(z[i]);
}

// ---------------- persistent kernel: 16 independent mb-chains, 32 steps each -----------
// 8 warps: wm = warp>>2 (M 2x64), wn = warp&3. Warp wn owns n8-blocks {wn, wn+4, wn+8,
// wn+12} = gates i,f,g,o of hidden units [8wn, 8wn+8): epilogue fully register-local.
// CTA (mb,nb) at step t waits only for g_cnt[t-1][mb]==16 (its row block's producers).
__global__ __launch_bounds__(NTHR, 2)
void lstm_persist(const float* __restrict__ Wd) {
    extern __shared__ char dyn[];
    __shared__ float bias_sm[TN];
    __shared__ float wd_sm[2][32];
    __shared__ float part_sm[2][4][8][4][2][2];   // [wm][wn][gq][mi][rw][o]
    const int tid = threadIdx.x;
    const int lane = tid & 31, warp = tid >> 5;
    const int wm = warp >> 2, wn = warp & 3;
    const int mb = blockIdx.x, nb = blockIdx.y;

    if (tid < TN) bias_sm[tid] = g_bp[nb * TN + tid];
    if (tid < 64) wd_sm[tid >> 5][tid & 31] = Wd[(tid >> 5) * HID + nb * 32 + (tid & 31)];
    __syncthreads();

    // ---- cp.async plan: rows 0..31 (+32*i), quads 0..7; 4 A + 4 B 16B-copies/thread ----
    const int lrow = tid >> 3, lq = tid & 7;
    const size_t a_goff = (size_t)(mb * TM + lrow) * HID + lq * 8;
    const size_t b_goff = (size_t)(nb * TN + lrow) * HID + lq * 8;
    const uint32_t a_dst0 = AH_OFF + smoff64(lrow, lq);  // +4096 per 32 rows
    const uint32_t b_dst0 = BH_OFF + smoff64(lrow, lq);

    // precomputed swizzled ldsm base offsets (stage-relative)
    const int a_row = wm * 64 + (lane & 7) + ((lane >> 3) & 1) * 8;
    const int b_row = 8 * (4 * (lane >> 3) + wn) + (lane & 7);   // n8 block = g*4 + wn
    uint32_t a_base[4], b_base[4][2];
#pragma unroll
    for (int s = 0; s < 4; ++s) {
        a_base[s] = AH_OFF + smoff64(a_row, 2 * s + (lane >> 4));
        b_base[s][0] = BH_OFF + smoff64(b_row, 2 * s);
        b_base[s][1] = BH_OFF + smoff64(b_row, 2 * s + 1);
    }
    const int gq = lane >> 2, sq = lane & 3;
    const int uu = 8 * wn + 2 * sq;          // local hidden index (0..31)
    const int hu = nb * 32 + uu;

#pragma unroll 1
    for (int t = 0; t < PH; ++t) {
        // ---- wait for this row block's producers (chain-local, skew-tolerant) ----
        if (t > 0) {
            if (tid == 0) {
                volatile int* cp = &g_cnt[t - 1][mb];
                while (*cp < NNB) __nanosleep(64);
            }
            __syncthreads();
        }
        const __half* a_src = g_x + (size_t)t * SLAB + a_goff;
        const __half* b_src = ((t == 0) ? g_w0 : g_w) + b_goff;

        float acc[4][4][4];   // [mi][gate][frag]
#pragma unroll
        for (int mi = 0; mi < 4; ++mi)
#pragma unroll
            for (int g = 0; g < 4; ++g)
#pragma unroll
                for (int r = 0; r < 4; ++r) acc[mi][g][r] = 0.f;

        // ---- prologue: chunks 0,1 ----
#pragma unroll
        for (int p = 0; p < 2; ++p) {
            uint32_t sb = smem_u32(dyn + p * STAGE);
            int k0 = p * KC;
#pragma unroll
            for (int i = 0; i < 4; ++i) {
                cp16(sb + a_dst0 + 4096 * i, a_src + (size_t)(32 * i) * HID + k0);
                cp16(sb + b_dst0 + 4096 * i, b_src + (size_t)(32 * i) * HID + k0);
            }
            cp_commit();
        }

#pragma unroll
        for (int c = 0; c < NCH; ++c) {
            if (c + 2 < NCH) cp_wait<1>(); else cp_wait<0>();
            __syncthreads();                 // chunk c resident; stage (c-1)%3 drained
            if (c + 2 < NCH) {
                uint32_t sb = smem_u32(dyn + ((c + 2) % 3) * STAGE);
                int k0 = (c + 2) * KC;
#pragma unroll
                for (int i = 0; i < 4; ++i) {
                    cp16(sb + a_dst0 + 4096 * i, a_src + (size_t)(32 * i) * HID + k0);
                    cp16(sb + b_dst0 + 4096 * i, b_src + (size_t)(32 * i) * HID + k0);
                }
                cp_commit();
            }
            uint32_t st = smem_u32(dyn + (c % 3) * STAGE);
#pragma unroll
            for (int s = 0; s < 4; ++s) {
                uint32_t r0[4], r1[4];           // B frags per gate
                ldsm4(r0, st + b_base[s][0]);
                ldsm4(r1, st + b_base[s][1]);
#pragma unroll
                for (int mi = 0; mi < 4; ++mi) {
                    uint32_t ah[4];
                    ldsm4(ah, st + a_base[s] + 2048 * mi);
#pragma unroll
                    for (int g = 0; g < 4; ++g)
                        mma16816(acc[mi][g], ah, r0[g], r1[g]);
                }
            }
        }

        // ---- fused LSTM epilogue + projection partials ----
        __half* x_o = g_x + (size_t)(t + 1) * SLAB;
#pragma unroll
        for (int mi = 0; mi < 4; ++mi) {
#pragma unroll
            for (int rw = 0; rw < 2; ++rw) {
                int row = mb * TM + wm * 64 + mi * 16 + gq + rw * 8;
                size_t off = (size_t)row * HID + hu;
                float2 cold = (t == 0) ? make_float2(0.f, 0.f)
                                       : *(const float2*)(g_c + off);
                float hn[2], cn[2];
#pragma unroll
                for (int e = 0; e < 2; ++e) {
                    int r = 2 * rw + e, u = uu + e;
                    float gi = acc[mi][0][r] + bias_sm[u];
                    float gf = acc[mi][1][r] + bias_sm[32 + u];
                    float gg = acc[mi][2][r] + bias_sm[64 + u];
                    float go = acc[mi][3][r] + bias_sm[96 + u];
                    float co = e ? cold.y : cold.x;
                    float si = 1.f / (1.f + __expf(-gi));
                    float sf = 1.f / (1.f + __expf(-gf));
                    float so = 1.f / (1.f + __expf(-go));
                    float tg = 2.f / (1.f + __expf(-2.f * gg)) - 1.f;
                    cn[e] = fmaf(sf, co, si * tg);
                    float tc = 2.f / (1.f + __expf(-2.f * cn[e])) - 1.f;
                    hn[e] = so * tc;
                }
                *(float2*)(g_c + off) = make_float2(cn[0], cn[1]);
                __half2 h2;
                h2.x = __float2half_rn(hn[0]); h2.y = __float2half_rn(hn[1]);
                *(__half2*)(x_o + off) = h2;
                float p0 = hn[0] * wd_sm[0][uu] + hn[1] * wd_sm[0][uu + 1];
                float p1 = hn[0] * wd_sm[1][uu] + hn[1] * wd_sm[1][uu + 1];
                p0 += __shfl_xor_sync(0xffffffffu, p0, 1);
                p0 += __shfl_xor_sync(0xffffffffu, p0, 2);
                p1 += __shfl_xor_sync(0xffffffffu, p1, 1);
                p1 += __shfl_xor_sync(0xffffffffu, p1, 2);
                if (sq == 0) {
                    part_sm[wm][wn][gq][mi][rw][0] = p0;
                    part_sm[wm][wn][gq][mi][rw][1] = p1;
                }
            }
        }
        __syncthreads();
        // 256 threads: one (wm,gq,mi,rw,o) entry each, fixed-order sum over wn
        {
            int o  = tid & 1;
            int rw = (tid >> 1) & 1;
            int mi = (tid >> 2) & 3;
            int gq2 = (tid >> 4) & 7;
            int wm2 = tid >> 7;
            float s = part_sm[wm2][0][gq2][mi][rw][o] + part_sm[wm2][1][gq2][mi][rw][o]
                    + part_sm[wm2][2][gq2][mi][rw][o] + part_sm[wm2][3][gq2][mi][rw][o];
            int row = mb * TM + wm2 * 64 + mi * 16 + gq2 + rw * 8;
            g_part[(((size_t)t * NNB + nb) * BSZ + row) * 2 + o] = s;
        }
        // ---- publish: this CTA's slice of x_{t+1} is written ----
        __threadfence();
        __syncthreads();
        if (tid == 0) atomicAdd(&g_cnt[t][mb], 1);
    }
}

// ---------------- final: reduce projection partials over nb ----------------
__global__ void out_reduce(const float* __restrict__ bd, float* __restrict__ Y) {
    int i = blockIdx.x * 256 + threadIdx.x;    // i = (t*2+o)*BSZ + row
    if (i >= PH * 2 * BSZ) return;
    int row = i & (BSZ - 1);
    int to = i >> 11;                           // t*2+o
    int o = to & 1, t = to >> 1;
    float s = bd[o];
#pragma unroll
    for (int nb = 0; nb < NNB; ++nb)
        s += g_part[(((size_t)t * NNB + nb) * BSZ + row) * 2 + o];
    Y[(size_t)row * (PH * 2) + t * 2 + o] = s;
}

extern "C" void kernel_launch(void* const* d_in, const int* in_sizes, int n_in,
                              void* d_out, int out_size) {
    // metadata order: hist, z, W_ih, W_hh, b_ih, b_hh, W_d, b_d
    const float* z   = (const float*)d_in[1];
    const float* Wih = (const float*)d_in[2];
    const float* Whh = (const float*)d_in[3];
    const float* bih = (const float*)d_in[4];
    const float* bhh = (const float*)d_in[5];
    const float* Wd  = (const float*)d_in[6];
    const float* bd  = (const float*)d_in[7];
    float* Y = (float*)d_out;

    cudaFuncSetAttribute(lstm_persist, cudaFuncAttributeMaxDynamicSharedMemorySize, SMEM_DYN);

    prep_w<<<(FOURH * HID + 255) / 256, 256>>>(Wih, Whh, bih, bhh);
    prep_z<<<(BSZ * HID + 255) / 256, 256>>>(z);

    dim3 grid(NMB, NNB);   // 16 x 16 = 256 CTAs, all co-resident (2/SM)
    lstm_persist<<<grid, NTHR, SMEM_DYN>>>(Wd);
    out_reduce<<<(PH * 2 * BSZ + 255) / 256, 256>>>(bd, Y);
}

// round 17
// speedup vs baseline: 1.0333x; 1.0333x over previous
#include <cuda_runtime.h>
#include <cuda_fp16.h>
#include <math.h>
#include <stdint.h>

#define HID   512
#define PH    32
#define BSZ   2048
#define FOURH 2048
#define SLAB  (BSZ * HID)

#define TM 256
#define TN 128
#define KC 64
#define NCH (HID / KC)   // 8 k-chunks
#define NTHR 512
#define NMB2 (BSZ / TM)     // 8 row-blocks
#define NNB  (FOURH / TN)   // 16 nb tiles

// dynamic smem layout (byte offsets, relative to dyn): B resident 8 chunks x 16KB,
// then 2 A stages x 32KB
#define B_OFF  0
#define A_OFF  131072
#define ASTG   32768
#define SMEM_DYN (131072 + 2 * ASTG)   // 192KB, 1 CTA/SM

// ---------------- static device scratch ----------------
__device__ __half g_x[(PH + 1) * (size_t)SLAB];   // x_t (fp16), t=0..PH
__device__ __half g_w [FOURH * HID];   // fp16(W_ih + W_hh), permuted
__device__ __half g_w0[FOURH * HID];   // fp16(W_ih), permuted (step 0)
__device__ float g_bp[FOURH];
__device__ float g_c[(size_t)BSZ * HID];
__device__ float g_part[(size_t)PH * NNB * BSZ * 2];   // projection partials
__device__ int   g_cnt[PH][NMB2];                      // per-(t,row-block) counters

// ---------------- helpers ----------------
__device__ __forceinline__ uint32_t smem_u32(const void* p) {
    uint32_t a;
    asm("{ .reg .u64 t; cvta.to.shared.u64 t, %1; cvt.u32.u64 %0, t; }" : "=r"(a) : "l"(p));
    return a;
}
// 128B rows, 8 x 16B quads, XOR-swizzled: conflict-free for cp.async stores and ldmatrix
__device__ __forceinline__ uint32_t smoff64(int row, int q) {
    return (uint32_t)((row << 7) + (((q) ^ (row & 7)) << 4));
}
__device__ __forceinline__ void cp16(uint32_t dst, const void* src) {
    asm volatile("cp.async.cg.shared.global [%0], [%1], 16;" :: "r"(dst), "l"(src));
}
__device__ __forceinline__ void cp_commit() { asm volatile("cp.async.commit_group;"); }
template <int N>
__device__ __forceinline__ void cp_wait() {
    asm volatile("cp.async.wait_group %0;" :: "n"(N) : "memory");
}
__device__ __forceinline__ void ldsm4(uint32_t* r, uint32_t addr) {
    asm volatile("ldmatrix.sync.aligned.m8n8.x4.shared.b16 {%0,%1,%2,%3}, [%4];"
        : "=r"(r[0]), "=r"(r[1]), "=r"(r[2]), "=r"(r[3]) : "r"(addr));
}
__device__ __forceinline__ void mma16816(float* c, const uint32_t* a,
                                         uint32_t b0, uint32_t b1) {
    asm volatile(
        "mma.sync.aligned.m16n8k16.row.col.f32.f16.f16.f32 "
        "{%0,%1,%2,%3}, {%4,%5,%6,%7}, {%8,%9}, {%0,%1,%2,%3};"
        : "+f"(c[0]), "+f"(c[1]), "+f"(c[2]), "+f"(c[3])
        : "r"(a[0]), "r"(a[1]), "r"(a[2]), "r"(a[3]), "r"(b0), "r"(b1));
}

// ---------------- prep ----------------
// W row r=q*512+hu -> rp = (hu/32)*128 + q*32 + (hu%32): N-tile nb holds 32 units x 4 gates
__global__ void prep_w(const float* __restrict__ Wih, const float* __restrict__ Whh,
                       const float* __restrict__ bih, const float* __restrict__ bhh) {
    int idx = blockIdx.x * blockDim.x + threadIdx.x;
    if (idx >= FOURH * HID) return;
    int r = idx / HID, k = idx - r * HID;
    int q = r >> 9, hu = r & 511;
    int rp = ((hu >> 5) << 7) + (q << 5) + (hu & 31);
    size_t o = (size_t)rp * HID + k;
    g_w0[o] = __float2half_rn(Wih[idx]);
    g_w [o] = __float2half_rn(Wih[idx] + Whh[idx]);
    if (k == 0) g_bp[rp] = bih[r] + bhh[r];
}
__global__ void prep_z(const float* __restrict__ z) {
    int i = blockIdx.x * blockDim.x + threadIdx.x;
    if (i < PH * NMB2) ((int*)g_cnt)[i] = 0;   // reset chain counters every launch
    if (i >= BSZ * HID) return;
    g_x[i] = __float2half_rn(z[i]);
}

// ---------------- persistent kernel: B smem-resident, A streamed per step -------------
// 16 warps: wm = warp>>2 (M 4x64), wn = warp&3. Warp wn owns n8-blocks {wn, wn+4, wn+8,
// wn+12} = gates i,f,g,o of hidden units [8wn, 8wn+8): epilogue fully register-local.
// CTA (mb2,nb) at step t waits only for g_cnt[t-1][mb2]==16 (its row block's producers).
__global__ __launch_bounds__(NTHR, 1)
void lstm_persist(const float* __restrict__ Wd) {
    extern __shared__ char dyn[];
    __shared__ float bias_sm[TN];
    __shared__ float wd_sm[2][32];
    __shared__ float part_sm[4][4][8][4][2][2];   // [wm][wn][gq][mi][rw][o]
    const int tid = threadIdx.x;
    const int lane = tid & 31, warp = tid >> 5;
    const int wm = warp >> 2, wn = warp & 3;
    const int mb2 = blockIdx.x, nb = blockIdx.y;
    const uint32_t sbase = smem_u32(dyn);           // <-- the R16 bug: this was missing

    if (tid < TN) bias_sm[tid] = g_bp[nb * TN + tid];
    if (tid < 64) wd_sm[tid >> 5][tid & 31] = Wd[(tid >> 5) * HID + nb * 32 + (tid & 31)];

    // ---- cp.async plans (all smem addresses include sbase) ----
    const int lrow = tid >> 3, lq = tid & 7;           // row 0..63, quad 0..7
    const size_t a_goff = (size_t)(mb2 * TM + lrow) * HID + lq * 8;
    const uint32_t a_dst0 = sbase + A_OFF + smoff64(lrow, lq); // +8192 per 64 rows
    const size_t b_goff = (size_t)(nb * TN + lrow) * HID + lq * 8;
    const uint32_t b_dst0 = sbase + B_OFF + smoff64(lrow, lq);

    // ldsm base offsets (include sbase)
    const int a_row = wm * 64 + (lane & 7) + ((lane >> 3) & 1) * 8;
    const int b_row = 8 * (4 * (lane >> 3) + wn) + (lane & 7);   // n8 block = g*4 + wn
    uint32_t a_base[4], b_base[4][2];
#pragma unroll
    for (int s = 0; s < 4; ++s) {
        a_base[s] = sbase + A_OFF + smoff64(a_row, 2 * s + (lane >> 4));
        b_base[s][0] = sbase + B_OFF + smoff64(b_row, 2 * s);
        b_base[s][1] = sbase + B_OFF + smoff64(b_row, 2 * s + 1);
    }
    const int gq = lane >> 2, sq = lane & 3;
    const int uu = 8 * wn + 2 * sq;          // local hidden index (0..31)
    const int hu = nb * 32 + uu;

    // ---- initial B load: all 8 chunks from g_w0 (one commit group) ----
#pragma unroll
    for (int ch = 0; ch < NCH; ++ch) {
#pragma unroll
        for (int i = 0; i < 2; ++i)
            cp16(b_dst0 + ch * 16384 + 8192 * i,
                 g_w0 + b_goff + (size_t)(64 * i) * HID + ch * KC);
    }
    cp_commit();
    __syncthreads();   // bias/wd visible

#pragma unroll 1
    for (int t = 0; t < PH; ++t) {
        if (t > 0) {
            if (tid == 0) {
                volatile int* cp = &g_cnt[t - 1][mb2];
                while (*cp < NNB) __nanosleep(64);
            }
            __syncthreads();
        }
        const __half* a_src = g_x + (size_t)t * SLAB + a_goff;

        float acc[4][4][4];   // [mi][gate][frag]
#pragma unroll
        for (int mi = 0; mi < 4; ++mi)
#pragma unroll
            for (int g = 0; g < 4; ++g)
#pragma unroll
                for (int r = 0; r < 4; ++r) acc[mi][g][r] = 0.f;

        // A chunk 0 -> stage 0
#pragma unroll
        for (int i = 0; i < 4; ++i)
            cp16(a_dst0 + 8192 * i, a_src + (size_t)(64 * i) * HID);
        cp_commit();

#pragma unroll 1
        for (int ch = 0; ch < NCH; ++ch) {
            cp_wait<0>();                    // chunk ch (and anything older) resident
            __syncthreads();                 // all warps past prior stage reads
            if (ch + 1 < NCH) {              // prefetch A chunk ch+1 into other stage
                uint32_t ad = a_dst0 + ((ch + 1) & 1) * ASTG;
                int k0 = (ch + 1) * KC;
#pragma unroll
                for (int i = 0; i < 4; ++i)
                    cp16(ad + 8192 * i, a_src + (size_t)(64 * i) * HID + k0);
                cp_commit();
            }
            const uint32_t a_st = (uint32_t)((ch & 1) * ASTG);
            const uint32_t b_st = (uint32_t)(ch * 16384);
#pragma unroll
            for (int s = 0; s < 4; ++s) {
                uint32_t r0[4], r1[4];           // B frags per gate (resident smem)
                ldsm4(r0, b_st + b_base[s][0]);
                ldsm4(r1, b_st + b_base[s][1]);
#pragma unroll
                for (int mi = 0; mi < 4; ++mi) {
                    uint32_t ah[4];
                    ldsm4(ah, a_st + a_base[s] + 2048 * mi);
#pragma unroll
                    for (int g = 0; g < 4; ++g)
                        mma16816(acc[mi][g], ah, r0[g], r1[g]);
                }
            }
        }

        // after step 0: swap resident B to the merged weights (overlaps epilogue)
        if (t == 0) {
            __syncthreads();                 // everyone done reading B (w0)
#pragma unroll
            for (int ch = 0; ch < NCH; ++ch) {
#pragma unroll
                for (int i = 0; i < 2; ++i)
                    cp16(b_dst0 + ch * 16384 + 8192 * i,
                         g_w + b_goff + (size_t)(64 * i) * HID + ch * KC);
            }
            cp_commit();                     // drained by next step's first cp_wait<0>
        }

        // ---- fused LSTM epilogue + projection partials ----
        __half* x_o = g_x + (size_t)(t + 1) * SLAB;
#pragma unroll
        for (int mi = 0; mi < 4; ++mi) {
#pragma unroll
            for (int rw = 0; rw < 2; ++rw) {
                int row = mb2 * TM + wm * 64 + mi * 16 + gq + rw * 8;
                size_t off = (size_t)row * HID + hu;
                float2 cold = (t == 0) ? make_float2(0.f, 0.f)
                                       : *(const float2*)(g_c + off);
                float hn[2], cn[2];
#pragma unroll
                for (int e = 0; e < 2; ++e) {
                    int r = 2 * rw + e, u = uu + e;
                    float gi = acc[mi][0][r] + bias_sm[u];
                    float gf = acc[mi][1][r] + bias_sm[32 + u];
                    float gg = acc[mi][2][r] + bias_sm[64 + u];
                    float go = acc[mi][3][r] + bias_sm[96 + u];
                    float co = e ? cold.y : cold.x;
                    float si = 1.f / (1.f + __expf(-gi));
                    float sf = 1.f / (1.f + __expf(-gf));
                    float so = 1.f / (1.f + __expf(-go));
                    float tg = 2.f / (1.f + __expf(-2.f * gg)) - 1.f;
                    cn[e] = fmaf(sf, co, si * tg);
                    float tc = 2.f / (1.f + __expf(-2.f * cn[e])) - 1.f;
                    hn[e] = so * tc;
                }
                *(float2*)(g_c + off) = make_float2(cn[0], cn[1]);
                __half2 h2;
                h2.x = __float2half_rn(hn[0]); h2.y = __float2half_rn(hn[1]);
                *(__half2*)(x_o + off) = h2;
                float p0 = hn[0] * wd_sm[0][uu] + hn[1] * wd_sm[0][uu + 1];
                float p1 = hn[0] * wd_sm[1][uu] + hn[1] * wd_sm[1][uu + 1];
                p0 += __shfl_xor_sync(0xffffffffu, p0, 1);
                p0 += __shfl_xor_sync(0xffffffffu, p0, 2);
                p1 += __shfl_xor_sync(0xffffffffu, p1, 1);
                p1 += __shfl_xor_sync(0xffffffffu, p1, 2);
                if (sq == 0) {
                    part_sm[wm][wn][gq][mi][rw][0] = p0;
                    part_sm[wm][wn][gq][mi][rw][1] = p1;
                }
            }
        }
        __syncthreads();
        // 512 threads: one (wm,gq,mi,rw,o) entry each, fixed-order sum over wn
        {
            int o  = tid & 1;
            int rw = (tid >> 1) & 1;
            int mi = (tid >> 2) & 3;
            int gq2 = (tid >> 4) & 7;
            int wm2 = (tid >> 7) & 3;
            float s = part_sm[wm2][0][gq2][mi][rw][o] + part_sm[wm2][1][gq2][mi][rw][o]
                    + part_sm[wm2][2][gq2][mi][rw][o] + part_sm[wm2][3][gq2][mi][rw][o];
            int row = mb2 * TM + wm2 * 64 + mi * 16 + gq2 + rw * 8;
            g_part[(((size_t)t * NNB + nb) * BSZ + row) * 2 + o] = s;
        }
        // ---- publish: this CTA's slice of x_{t+1} is written ----
        __threadfence();
        __syncthreads();
        if (tid == 0) atomicAdd(&g_cnt[t][mb2], 1);
    }
}

// ---------------- final: reduce projection partials over nb ----------------
__global__ void out_reduce(const float* __restrict__ bd, float* __restrict__ Y) {
    int i = blockIdx.x * 256 + threadIdx.x;    // i = (t*2+o)*BSZ + row
    if (i >= PH * 2 * BSZ) return;
    int row = i & (BSZ - 1);
    int to = i >> 11;                           // t*2+o
    int o = to & 1, t = to >> 1;
    float s = bd[o];
#pragma unroll
    for (int nb = 0; nb < NNB; ++nb)
        s += g_part[(((size_t)t * NNB + nb) * BSZ + row) * 2 + o];
    Y[(size_t)row * (PH * 2) + t * 2 + o] = s;
}

extern "C" void kernel_launch(void* const* d_in, const int* in_sizes, int n_in,
                              void* d_out, int out_size) {
    // metadata order: hist, z, W_ih, W_hh, b_ih, b_hh, W_d, b_d
    const float* z   = (const float*)d_in[1];
    const float* Wih = (const float*)d_in[2];
    const float* Whh = (const float*)d_in[3];
    const float* bih = (const float*)d_in[4];
    const float* bhh = (const float*)d_in[5];
    const float* Wd  = (const float*)d_in[6];
    const float* bd  = (const float*)d_in[7];
    float* Y = (float*)d_out;

    cudaFuncSetAttribute(lstm_persist, cudaFuncAttributeMaxDynamicSharedMemorySize, SMEM_DYN);

    prep_w<<<(FOURH * HID + 255) / 256, 256>>>(Wih, Whh, bih, bhh);
    prep_z<<<(BSZ * HID + 255) / 256, 256>>>(z);

    dim3 grid(NMB2, NNB);   // 8 x 16 = 128 CTAs, 1 per SM, all co-resident
    lstm_persist<<<grid, NTHR, SMEM_DYN>>>(Wd);
    out_reduce<<<(PH * 2 * BSZ + 255) / 256, 256>>>(bd, Y);
}